// round 14
// baseline (speedup 1.0000x reference)
#include <cuda_runtime.h>
#include <cuda_fp16.h>
#include <math.h>

#define N_NODES 50000
#define N_EDGES 800000
#define NB_SCAN ((N_NODES + 1023) / 1024)   // 49 (< 148 SMs -> all co-resident)

// Scratch (device globals — allocation-free per harness rules)
__device__ int   g_degi[N_NODES];
__device__ int   g_off[N_NODES];
__device__ int   g_cursor[N_NODES];
__device__ int   g_bsum[64];
__device__ int   g_scan_ctr;
__device__ int   g_esrc[N_EDGES];       // CSR payload: src node of each in-edge of n
__device__ float g_dinv[N_NODES];
__device__ __align__(16) __half g_th[N_NODES * 64];   // t = x @ W1 (fp16)
__device__ __align__(16) float  g_agg[N_NODES * 64];  // normalized aggregation
__device__ __align__(16) __half g_Ph[N_NODES * 128];  // [A | B] per-node precompute (fp16)
__device__ __align__(16) __half g_eah[N_EDGES * 16];  // ea pre-rounded to fp16

// ---- packed f32x2 helpers (sm_103a FFMA2 — ptxas never auto-fuses these) ----
typedef unsigned long long ull;
__device__ __forceinline__ ull pack2(float v) {
    ull r; asm("mov.b64 %0, {%1,%2};" : "=l"(r) : "f"(v), "f"(v)); return r;
}
__device__ __forceinline__ void unpack2(ull v, float& lo, float& hi) {
    asm("mov.b64 {%0,%1}, %2;" : "=f"(lo), "=f"(hi) : "l"(v));
}
__device__ __forceinline__ void fma2(ull& d, ull a, ull b) {
    asm("fma.rn.f32x2 %0, %1, %2, %0;" : "+l"(d) : "l"(a), "l"(b));
}
__device__ __forceinline__ unsigned int hadd2(unsigned int a, unsigned int b) {
    unsigned int r; asm("add.rn.f16x2 %0, %1, %2;" : "=r"(r) : "r"(a), "r"(b)); return r;
}
__device__ __forceinline__ float2 h2f2(unsigned int h) {
    __half2 hv = *reinterpret_cast<__half2*>(&h);
    return __half22float2(hv);
}
__device__ __forceinline__ unsigned int f2h2(float lo, float hi) {
    __half2 p = __floats2half2_rn(lo, hi);
    return *(unsigned int*)&p;
}

__global__ void k_count(const int* __restrict__ dst) {
    int e = blockIdx.x * blockDim.x + threadIdx.x;
    if (e == 0) g_scan_ctr = 0;   // reset fused-scan barrier for this replay
    if (e < N_EDGES) atomicAdd(&g_degi[dst[e]], 1);
}

// Fused exclusive scan of g_degi -> g_off + cursor init + dinv.
// One parallel grid barrier (all NB_SCAN blocks co-resident; counter reset by k_count).
__global__ void k_scan() {
    int tid = threadIdx.x;
    int b = blockIdx.x;
    int i = b * 1024 + tid;
    int v = (i < N_NODES) ? g_degi[i] : 0;
    int lane = tid & 31, wid = tid >> 5;
    int s = v;
#pragma unroll
    for (int o = 1; o < 32; o <<= 1) {
        int t = __shfl_up_sync(0xffffffffu, s, o);
        if (lane >= o) s += t;
    }
    __shared__ int ws[32];
    __shared__ int sb[64];
    __shared__ int base_s;
    if (lane == 31) ws[wid] = s;
    __syncthreads();
    if (wid == 0) {
        int t = ws[lane];
        int ss = t;
#pragma unroll
        for (int o = 1; o < 32; o <<= 1) {
            int u = __shfl_up_sync(0xffffffffu, ss, o);
            if (lane >= o) ss += u;
        }
        ws[lane] = ss - t;
    }
    __syncthreads();
    int excl = ws[wid] + s - v;
    if (tid == 1023) {
        g_bsum[b] = ws[31] + s;           // block total
        __threadfence();
        atomicAdd(&g_scan_ctr, 1);
    }
    if (tid == 0) {                        // parallel barrier: wait for ALL blocks
        while (atomicAdd(&g_scan_ctr, 0) < NB_SCAN) { }
    }
    __syncthreads();
    __threadfence();
    if (tid < 64) sb[tid] = (tid < NB_SCAN) ? g_bsum[tid] : 0;
    __syncthreads();
    if (tid == 0) {
        int base = 0;
        for (int j = 0; j < b; j++) base += sb[j];
        base_s = base;
    }
    __syncthreads();
    if (i < N_NODES) {
        int o = excl + base_s;
        g_off[i] = o;
        g_cursor[i] = o;
        g_dinv[i] = rsqrtf((float)(g_degi[i] + 1));
    }
}

// CSR fill: store src id directly
__global__ void k_fill(const int* __restrict__ src, const int* __restrict__ dst) {
    int e = blockIdx.x * blockDim.x + threadIdx.x;
    if (e >= N_EDGES) return;
    int pos = atomicAdd(&g_cursor[dst[e]], 1);
    g_esrc[pos] = src[e];
}

// t = x @ W1 (fp16 out) — row-major tiles, float4 fills, 4-k chunked inner loop.
__global__ void k_mm1(const float* __restrict__ x, const float* __restrict__ W1) {
    __shared__ float sW[64 * 64];        // [k][j]
    __shared__ float sx[64 * 68];        // row-major [r][k], pitch 68 floats
    int tid = threadIdx.x;
    int row0 = blockIdx.x * 64;
    const float4* W4 = (const float4*)W1;
    float4* sW4s = (float4*)sW;
    for (int i = tid; i < 1024; i += 256) sW4s[i] = W4[i];
    const float4* x4 = (const float4*)x;
    float4* sx4 = (float4*)sx;
    for (int i = tid; i < 1024; i += 256) {
        int r = i >> 4, q = i & 15;
        int row = row0 + r;
        float4 v = (row < N_NODES) ? x4[row * 16 + q] : make_float4(0.f, 0.f, 0.f, 0.f);
        sx4[r * 17 + q] = v;
    }
    __syncthreads();
    int ty = tid >> 4, tx = tid & 15;
    ull c0a = 0, c0b = 0, c1a = 0, c1b = 0, c2a = 0, c2b = 0, c3a = 0, c3b = 0;
    const ulonglong2* sWu = (const ulonglong2*)sW;
    int rb = ty * 4;
#pragma unroll
    for (int k4 = 0; k4 < 16; k4++) {
        float4 xv0 = *(const float4*)&sx[(rb + 0) * 68 + k4 * 4];
        float4 xv1 = *(const float4*)&sx[(rb + 1) * 68 + k4 * 4];
        float4 xv2 = *(const float4*)&sx[(rb + 2) * 68 + k4 * 4];
        float4 xv3 = *(const float4*)&sx[(rb + 3) * 68 + k4 * 4];
        const float* p0 = &xv0.x;
        const float* p1 = &xv1.x;
        const float* p2 = &xv2.x;
        const float* p3 = &xv3.x;
#pragma unroll
        for (int j = 0; j < 4; j++) {
            int k = k4 * 4 + j;
            ulonglong2 w = sWu[k * 16 + tx];
            ull X0 = pack2(p0[j]), X1 = pack2(p1[j]), X2 = pack2(p2[j]), X3 = pack2(p3[j]);
            fma2(c0a, X0, w.x); fma2(c0b, X0, w.y);
            fma2(c1a, X1, w.x); fma2(c1b, X1, w.y);
            fma2(c2a, X2, w.x); fma2(c2b, X2, w.y);
            fma2(c3a, X3, w.x); fma2(c3b, X3, w.y);
        }
    }
    uint2* th2 = (uint2*)g_th;   // 16 uint2 per node row (64 halves)
    int row = row0 + rb;
    float lo, hi;
    uint2 u;
    unpack2(c0a, lo, hi); u.x = f2h2(lo, hi);
    unpack2(c0b, lo, hi); u.y = f2h2(lo, hi);
    if (row + 0 < N_NODES) th2[(row + 0) * 16 + tx] = u;
    unpack2(c1a, lo, hi); u.x = f2h2(lo, hi);
    unpack2(c1b, lo, hi); u.y = f2h2(lo, hi);
    if (row + 1 < N_NODES) th2[(row + 1) * 16 + tx] = u;
    unpack2(c2a, lo, hi); u.x = f2h2(lo, hi);
    unpack2(c2b, lo, hi); u.y = f2h2(lo, hi);
    if (row + 2 < N_NODES) th2[(row + 2) * 16 + tx] = u;
    unpack2(c3a, lo, hi); u.x = f2h2(lo, hi);
    unpack2(c3b, lo, hi); u.y = f2h2(lo, hi);
    if (row + 3 < N_NODES) th2[(row + 3) * 16 + tx] = u;
}

// ea -> fp16 (bit-identical to the rounding k_edge used to do inline).
// 3.2M float4 units; grid-stride free since 12.8M floats / 4 = 3.2M threads.
__global__ void k_eahalf(const float* __restrict__ ea) {
    int i = blockIdx.x * 256 + threadIdx.x;
    float4 v = ((const float4*)ea)[i];
    ((uint2*)g_eah)[i] = make_uint2(f2h2(v.x, v.y), f2h2(v.z, v.w));
}

// CSR gather-reduce over fp16 t, no atomics. 16 threads/node, uint2 (4 cols) each.
__global__ void k_agg() {
    unsigned int gid = blockIdx.x * blockDim.x + threadIdx.x;
    unsigned int n = gid >> 4;
    int c = gid & 15;
    if (n >= N_NODES) return;
    const uint2* t2 = (const uint2*)g_th;
    float dn = g_dinv[n];
    uint2 u = t2[n * 16 + c];
    float2 s01 = h2f2(u.x), s23 = h2f2(u.y);
    float w2 = dn * dn;
    float4 acc = make_float4(s01.x * w2, s01.y * w2, s23.x * w2, s23.y * w2);
    int beg = g_off[n];
    int end = beg + g_degi[n];
#pragma unroll 4
    for (int j = beg; j < end; j++) {
        int s = g_esrc[j];             // broadcast across the 16-thread group
        float w = dn * g_dinv[s];
        uint2 uu = t2[s * 16 + c];
        float2 a01 = h2f2(uu.x), a23 = h2f2(uu.y);
        acc.x += a01.x * w; acc.y += a01.y * w;
        acc.z += a23.x * w; acc.w += a23.y * w;
    }
    ((float4*)g_agg)[n * 16 + c] = acc;
}

// h = relu(agg + b1); P = [h@Wm1[0:64]+bm1 | h@Wm1[64:128]] stored fp16.
// Tensor-core version: 8 warps/block, each owns a 16-row x 64-col output tile.
__global__ void k_mm2(const float* __restrict__ Wm1, const float* __restrict__ b1,
                      const float* __restrict__ bm1) {
    __shared__ unsigned short sH[64 * 72];   // h fp16, pitch 72 halves = 36 words
    __shared__ uint2 sB[4 * 16 * 32];        // B frags: [kt][ntile][lane] = 16KB
    __shared__ float sbm[64];
    int tid = threadIdx.x;
    int row0 = blockIdx.x * 64;

    // --- h tile: relu(agg + b1) -> fp16 smem ---
    {
        const float4* agg4 = (const float4*)g_agg;
        const float4* b14 = (const float4*)b1;
        unsigned int* H32 = (unsigned int*)sH;
        for (int i = tid; i < 1024; i += 256) {
            int r = i >> 4, qd = i & 15;
            int row = row0 + r;
            unsigned int w0 = 0, w1 = 0;
            if (row < N_NODES) {
                float4 a = agg4[row * 16 + qd];
                float4 b = b14[qd];
                float vx = fmaxf(a.x + b.x, 0.f), vy = fmaxf(a.y + b.y, 0.f);
                float vz = fmaxf(a.z + b.z, 0.f), vw = fmaxf(a.w + b.w, 0.f);
                w0 = f2h2(vx, vy); w1 = f2h2(vz, vw);
            }
            H32[r * 36 + qd * 2 + 0] = w0;
            H32[r * 36 + qd * 2 + 1] = w1;
        }
    }
    // --- B fragments: effective weight We[k][col] = col<64 ? Wm1[k][col] : Wm1[64+k][col-64] ---
    for (int i = tid; i < 2048; i += 256) {
        int kt = i >> 9, rem = i & 511;
        int nt = rem >> 5, lane2 = rem & 31;
        int gg = lane2 >> 2, qq = lane2 & 3;
        int colg = nt * 8 + gg;
        int rbase = (colg < 64) ? 0 : 64;
        int col = colg & 63;
        int k0 = kt * 16 + 2 * qq;
        uint2 v;
        v.x = f2h2(Wm1[(rbase + k0) * 64 + col],     Wm1[(rbase + k0 + 1) * 64 + col]);
        v.y = f2h2(Wm1[(rbase + k0 + 8) * 64 + col], Wm1[(rbase + k0 + 9) * 64 + col]);
        sB[(kt * 16 + nt) * 32 + lane2] = v;
    }
    if (tid < 64) sbm[tid] = bm1[tid];
    __syncthreads();

    int lane = tid & 31, w = tid >> 5;
    int g = lane >> 2, q = lane & 3;
    int rt = w & 3, ch = w >> 2;      // row tile (16 rows), col half (64 cols)
    int rloc = rt * 16;
    float acc[8][4];
#pragma unroll
    for (int j = 0; j < 8; j++) { acc[j][0] = acc[j][1] = acc[j][2] = acc[j][3] = 0.f; }

    const unsigned int* H32 = (const unsigned int*)sH;
#pragma unroll
    for (int kt = 0; kt < 4; kt++) {
        int base = (rloc + g) * 36 + kt * 8;
        unsigned int a0 = H32[base + q];
        unsigned int a1 = H32[base + 8 * 36 + q];
        unsigned int a2 = H32[base + q + 4];
        unsigned int a3 = H32[base + 8 * 36 + q + 4];
#pragma unroll
        for (int j = 0; j < 8; j++) {
            int nt = ch * 8 + j;
            uint2 b = sB[(kt * 16 + nt) * 32 + lane];
            asm volatile(
                "mma.sync.aligned.m16n8k16.row.col.f32.f16.f16.f32 "
                "{%0,%1,%2,%3}, {%4,%5,%6,%7}, {%8,%9}, {%0,%1,%2,%3};"
                : "+f"(acc[j][0]), "+f"(acc[j][1]), "+f"(acc[j][2]), "+f"(acc[j][3])
                : "r"(a0), "r"(a1), "r"(a2), "r"(a3), "r"(b.x), "r"(b.y));
        }
    }

    // --- epilogue: +bm1 on A-half cols, fp16 pack, store to g_Ph ---
    unsigned int* Ph32 = (unsigned int*)g_Ph;   // 64 half2-words per node row
    int row_g0 = row0 + rloc + g;
    int row_g8 = row_g0 + 8;
#pragma unroll
    for (int j = 0; j < 8; j++) {
        int nt = ch * 8 + j;
        float c0 = acc[j][0], c1 = acc[j][1], c2 = acc[j][2], c3 = acc[j][3];
        if (ch == 0) {                 // cols nt*8+2q < 64: add bm1
            float2 bb = *(const float2*)&sbm[nt * 8 + 2 * q];
            c0 += bb.x; c1 += bb.y; c2 += bb.x; c3 += bb.y;
        }
        int cw = nt * 4 + q;
        if (row_g0 < N_NODES) Ph32[row_g0 * 64 + cw] = f2h2(c0, c1);
        if (row_g8 < N_NODES) Ph32[row_g8 * 64 + cw] = f2h2(c2, c3);
    }
}

// per-edge via tensor cores: G = ea@We on HMMA (m16n8k16), epilogue in-register.
// ea pre-rounded to fp16 in g_eah. Each warp owns 16 edges; block = 128 edges.
__global__ void k_edge(const int* __restrict__ src, const int* __restrict__ dst,
                       const float* __restrict__ Wm1,
                       const float* __restrict__ Wm2, const float* __restrict__ bm2,
                       float* __restrict__ out) {
    __shared__ __align__(16) unsigned short sEA[128 * 16];   // ea tile fp16, pitch 16 halves
    __shared__ unsigned int sB0[8 * 32], sB1[8 * 32];        // B fragments per (tile, lane)
    __shared__ float sW2[64];
    __shared__ float sb2;
    int tid = threadIdx.x;
    int lane = tid & 31, w = tid >> 5;
    int g = lane >> 2, q = lane & 3;
    // --- B fragments for We = Wm1 rows 128..143 (k=16 x n=64), col-tile = tid>>5 ---
    {
        int coln = (tid >> 5) * 8 + g;     // n-column for this (tile, lane)
        int k0 = 2 * q;
        sB0[tid] = f2h2(Wm1[(128 + k0) * 64 + coln],     Wm1[(128 + k0 + 1) * 64 + coln]);
        sB1[tid] = f2h2(Wm1[(128 + k0 + 8) * 64 + coln], Wm1[(128 + k0 + 9) * 64 + coln]);
    }
    if (tid < 64) sW2[tid] = Wm2[tid];
    if (tid == 0) sb2 = bm2[0];
    // --- ea tile from pre-halved g_eah: thread loads 8 halves (uint4 = 16B) ---
    {
        int eloc = tid >> 1, part = tid & 1;
        const uint4* s4 = (const uint4*)g_eah + ((size_t)blockIdx.x * 128 + eloc) * 2 + part;
        uint4 v = *s4;
        unsigned int* d16 = (unsigned int*)&sEA[eloc * 16 + part * 8];
        d16[0] = v.x; d16[1] = v.y; d16[2] = v.z; d16[3] = v.w;
    }
    __syncthreads();
    // --- per-warp: 16 edges [wbase, wbase+16) ---
    int wbase = w * 16;
    int r0 = wbase + g, r1 = wbase + g + 8;          // this thread's two edge rows
    unsigned int ebase = blockIdx.x * 128;
    int e0 = ebase + r0, e1 = ebase + r1;
    int s0 = src[e0], d0n = dst[e0];
    int s1 = src[e1], d1n = dst[e1];
    // A fragments (rows r0/r1 of ea tile, halves 2q..2q+1 and 2q+8..2q+9)
    const unsigned int* EA32 = (const unsigned int*)sEA;   // 8 words per edge row
    unsigned int a0 = EA32[r0 * 8 + q];
    unsigned int a1 = EA32[r1 * 8 + q];
    unsigned int a2 = EA32[r0 * 8 + q + 4];
    unsigned int a3 = EA32[r1 * 8 + q + 4];
    const unsigned int* Ph32 = (const unsigned int*)g_Ph;  // 64 half2-words per node
    float acc0 = 0.f, acc1 = 0.f;
#pragma unroll
    for (int j = 0; j < 8; j++) {
        float c0 = 0.f, c1 = 0.f, c2 = 0.f, c3 = 0.f;
        asm volatile(
            "mma.sync.aligned.m16n8k16.row.col.f32.f16.f16.f32 "
            "{%0,%1,%2,%3}, {%4,%5,%6,%7}, {%8,%9}, {%0,%1,%2,%3};"
            : "+f"(c0), "+f"(c1), "+f"(c2), "+f"(c3)
            : "r"(a0), "r"(a1), "r"(a2), "r"(a3),
              "r"(sB0[j * 32 + lane]), "r"(sB1[j * 32 + lane]));
        // cols for this thread: jc = j*8 + 2q, jc+1  -> half2 word j*4+q
        int cw = j * 4 + q;
        unsigned int pa0 = Ph32[s0 * 64 + cw];          // A half (cols 0..63)
        unsigned int pb0 = Ph32[d0n * 64 + 32 + cw];    // B half (cols 64..127)
        unsigned int pa1 = Ph32[s1 * 64 + cw];
        unsigned int pb1 = Ph32[d1n * 64 + 32 + cw];
        float2 h0 = h2f2(hadd2(pa0, pb0));
        float2 h1 = h2f2(hadd2(pa1, pb1));
        c0 = fmaxf(c0 + h0.x, 0.f); c1 = fmaxf(c1 + h0.y, 0.f);
        c2 = fmaxf(c2 + h1.x, 0.f); c3 = fmaxf(c3 + h1.y, 0.f);
        float2 w2v = *(const float2*)&sW2[j * 8 + 2 * q];
        acc0 += c0 * w2v.x + c1 * w2v.y;
        acc1 += c2 * w2v.x + c3 * w2v.y;
    }
    // reduce across the 4 lanes sharing each edge row (lanes g*4 .. g*4+3)
    acc0 += __shfl_xor_sync(0xffffffffu, acc0, 1);
    acc0 += __shfl_xor_sync(0xffffffffu, acc0, 2);
    acc1 += __shfl_xor_sync(0xffffffffu, acc1, 1);
    acc1 += __shfl_xor_sync(0xffffffffu, acc1, 2);
    if (q == 0) {
        out[e0] = 1.f / (1.f + __expf(-(acc0 + sb2)));
        out[e1] = 1.f / (1.f + __expf(-(acc1 + sb2)));
    }
}

extern "C" void kernel_launch(void* const* d_in, const int* in_sizes, int n_in,
                              void* d_out, int out_size) {
    const float* x   = (const float*)d_in[0];
    const int*   src = (const int*)d_in[1];
    const int*   dst = (const int*)d_in[2];
    const float* ea  = (const float*)d_in[3];
    const float* W1  = (const float*)d_in[4];
    const float* b1  = (const float*)d_in[5];
    const float* Wm1 = (const float*)d_in[6];
    const float* bm1 = (const float*)d_in[7];
    const float* Wm2 = (const float*)d_in[8];
    const float* bm2 = (const float*)d_in[9];
    float* out = (float*)d_out;
    (void)in_sizes; (void)n_in; (void)out_size;

    // One-time host-side setup (first call is the uncaptured correctness run;
    // no device memory is allocated here).
    static cudaStream_t s_side = nullptr;
    static cudaEvent_t  s_fork = nullptr, s_join = nullptr;
    static void* degi_ptr = nullptr;
    if (!s_side) {
        cudaStreamCreateWithFlags(&s_side, cudaStreamNonBlocking);
        cudaEventCreateWithFlags(&s_fork, cudaEventDisableTiming);
        cudaEventCreateWithFlags(&s_join, cudaEventDisableTiming);
        cudaGetSymbolAddress(&degi_ptr, g_degi);
    }

    // Fork: k_mm1 + ea fp16 pre-round (both graph-structure independent)
    // overlap the CSR build chain on the main (capture) stream.
    cudaEventRecord(s_fork, 0);
    cudaStreamWaitEvent(s_side, s_fork, 0);
    k_mm1<<<(N_NODES + 63) / 64, 256, 0, s_side>>>(x, W1);
    k_eahalf<<<(N_EDGES * 4) / 256, 256, 0, s_side>>>(ea);   // 12500 blocks
    cudaEventRecord(s_join, s_side);

    // Main stream: degree histogram -> fused scan -> CSR fill
    cudaMemsetAsync(degi_ptr, 0, N_NODES * sizeof(int), 0);
    k_count<<<(N_EDGES + 255) / 256, 256>>>(dst);
    k_scan<<<NB_SCAN, 1024>>>();
    k_fill<<<(N_EDGES + 255) / 256, 256>>>(src, dst);

    // Join: k_agg needs k_mm1 (t); k_edge needs g_eah (same side-stream order)
    cudaStreamWaitEvent(0, s_join, 0);
    k_agg<<<(N_NODES * 16 + 255) / 256, 256>>>();
    k_mm2<<<(N_NODES + 63) / 64, 256>>>(Wm1, b1, bm1);
    k_edge<<<N_EDGES / 128, 256>>>(src, dst, Wm1, Wm2, bm2, out);
}

// round 15
// speedup vs baseline: 1.0708x; 1.0708x over previous
#include <cuda_runtime.h>
#include <cuda_fp16.h>
#include <math.h>

#define N_NODES 50000
#define N_EDGES 800000
#define NB_SCAN ((N_NODES + 1023) / 1024)   // 49 (< 148 SMs -> all co-resident)

// Scratch (device globals — allocation-free per harness rules)
__device__ int   g_degi[N_NODES];
__device__ int   g_off[N_NODES];
__device__ int   g_cursor[N_NODES];
__device__ int   g_bsum[64];
__device__ int   g_scan_ctr;
__device__ int   g_esrc[N_EDGES];       // CSR payload: src node of each in-edge of n
__device__ float g_dinv[N_NODES];
__device__ __align__(16) __half g_th[N_NODES * 64];   // t = x @ W1 (fp16)
__device__ __align__(16) float  g_agg[N_NODES * 64];  // normalized aggregation
__device__ __align__(16) __half g_Ph[N_NODES * 128];  // [A | B] per-node precompute (fp16)

// ---- packed f32x2 helpers (sm_103a FFMA2 — ptxas never auto-fuses these) ----
typedef unsigned long long ull;
__device__ __forceinline__ ull pack2(float v) {
    ull r; asm("mov.b64 %0, {%1,%2};" : "=l"(r) : "f"(v), "f"(v)); return r;
}
__device__ __forceinline__ void unpack2(ull v, float& lo, float& hi) {
    asm("mov.b64 {%0,%1}, %2;" : "=f"(lo), "=f"(hi) : "l"(v));
}
__device__ __forceinline__ void fma2(ull& d, ull a, ull b) {
    asm("fma.rn.f32x2 %0, %1, %2, %0;" : "+l"(d) : "l"(a), "l"(b));
}
__device__ __forceinline__ unsigned int hadd2(unsigned int a, unsigned int b) {
    unsigned int r; asm("add.rn.f16x2 %0, %1, %2;" : "=r"(r) : "r"(a), "r"(b)); return r;
}
__device__ __forceinline__ float2 h2f2(unsigned int h) {
    __half2 hv = *reinterpret_cast<__half2*>(&h);
    return __half22float2(hv);
}
__device__ __forceinline__ unsigned int f2h2(float lo, float hi) {
    __half2 p = __floats2half2_rn(lo, hi);
    return *(unsigned int*)&p;
}

__global__ void k_count(const int* __restrict__ dst) {
    int e = blockIdx.x * blockDim.x + threadIdx.x;
    if (e == 0) g_scan_ctr = 0;   // reset fused-scan barrier for this replay
    if (e < N_EDGES) atomicAdd(&g_degi[dst[e]], 1);
}

// Fused exclusive scan of g_degi -> g_off + cursor init + dinv.
// One parallel grid barrier (all NB_SCAN blocks co-resident; counter reset by k_count).
__global__ void k_scan() {
    int tid = threadIdx.x;
    int b = blockIdx.x;
    int i = b * 1024 + tid;
    int v = (i < N_NODES) ? g_degi[i] : 0;
    int lane = tid & 31, wid = tid >> 5;
    int s = v;
#pragma unroll
    for (int o = 1; o < 32; o <<= 1) {
        int t = __shfl_up_sync(0xffffffffu, s, o);
        if (lane >= o) s += t;
    }
    __shared__ int ws[32];
    __shared__ int sb[64];
    __shared__ int base_s;
    if (lane == 31) ws[wid] = s;
    __syncthreads();
    if (wid == 0) {
        int t = ws[lane];
        int ss = t;
#pragma unroll
        for (int o = 1; o < 32; o <<= 1) {
            int u = __shfl_up_sync(0xffffffffu, ss, o);
            if (lane >= o) ss += u;
        }
        ws[lane] = ss - t;
    }
    __syncthreads();
    int excl = ws[wid] + s - v;
    if (tid == 1023) {
        g_bsum[b] = ws[31] + s;           // block total
        __threadfence();
        atomicAdd(&g_scan_ctr, 1);
    }
    if (tid == 0) {                        // parallel barrier: wait for ALL blocks
        while (atomicAdd(&g_scan_ctr, 0) < NB_SCAN) { }
    }
    __syncthreads();
    __threadfence();
    if (tid < 64) sb[tid] = (tid < NB_SCAN) ? g_bsum[tid] : 0;
    __syncthreads();
    if (tid == 0) {
        int base = 0;
        for (int j = 0; j < b; j++) base += sb[j];
        base_s = base;
    }
    __syncthreads();
    if (i < N_NODES) {
        int o = excl + base_s;
        g_off[i] = o;
        g_cursor[i] = o;
        g_dinv[i] = rsqrtf((float)(g_degi[i] + 1));
    }
}

// CSR fill: store src id directly
__global__ void k_fill(const int* __restrict__ src, const int* __restrict__ dst) {
    int e = blockIdx.x * blockDim.x + threadIdx.x;
    if (e >= N_EDGES) return;
    int pos = atomicAdd(&g_cursor[dst[e]], 1);
    g_esrc[pos] = src[e];
}

// t = x @ W1 (fp16 out) — row-major tiles, float4 fills, 4-k chunked inner loop.
__global__ void k_mm1(const float* __restrict__ x, const float* __restrict__ W1) {
    __shared__ float sW[64 * 64];        // [k][j]
    __shared__ float sx[64 * 68];        // row-major [r][k], pitch 68 floats
    int tid = threadIdx.x;
    int row0 = blockIdx.x * 64;
    const float4* W4 = (const float4*)W1;
    float4* sW4s = (float4*)sW;
    for (int i = tid; i < 1024; i += 256) sW4s[i] = W4[i];
    const float4* x4 = (const float4*)x;
    float4* sx4 = (float4*)sx;
    for (int i = tid; i < 1024; i += 256) {
        int r = i >> 4, q = i & 15;
        int row = row0 + r;
        float4 v = (row < N_NODES) ? x4[row * 16 + q] : make_float4(0.f, 0.f, 0.f, 0.f);
        sx4[r * 17 + q] = v;
    }
    __syncthreads();
    int ty = tid >> 4, tx = tid & 15;
    ull c0a = 0, c0b = 0, c1a = 0, c1b = 0, c2a = 0, c2b = 0, c3a = 0, c3b = 0;
    const ulonglong2* sWu = (const ulonglong2*)sW;
    int rb = ty * 4;
#pragma unroll
    for (int k4 = 0; k4 < 16; k4++) {
        float4 xv0 = *(const float4*)&sx[(rb + 0) * 68 + k4 * 4];
        float4 xv1 = *(const float4*)&sx[(rb + 1) * 68 + k4 * 4];
        float4 xv2 = *(const float4*)&sx[(rb + 2) * 68 + k4 * 4];
        float4 xv3 = *(const float4*)&sx[(rb + 3) * 68 + k4 * 4];
        const float* p0 = &xv0.x;
        const float* p1 = &xv1.x;
        const float* p2 = &xv2.x;
        const float* p3 = &xv3.x;
#pragma unroll
        for (int j = 0; j < 4; j++) {
            int k = k4 * 4 + j;
            ulonglong2 w = sWu[k * 16 + tx];
            ull X0 = pack2(p0[j]), X1 = pack2(p1[j]), X2 = pack2(p2[j]), X3 = pack2(p3[j]);
            fma2(c0a, X0, w.x); fma2(c0b, X0, w.y);
            fma2(c1a, X1, w.x); fma2(c1b, X1, w.y);
            fma2(c2a, X2, w.x); fma2(c2b, X2, w.y);
            fma2(c3a, X3, w.x); fma2(c3b, X3, w.y);
        }
    }
    uint2* th2 = (uint2*)g_th;   // 16 uint2 per node row (64 halves)
    int row = row0 + rb;
    float lo, hi;
    uint2 u;
    unpack2(c0a, lo, hi); u.x = f2h2(lo, hi);
    unpack2(c0b, lo, hi); u.y = f2h2(lo, hi);
    if (row + 0 < N_NODES) th2[(row + 0) * 16 + tx] = u;
    unpack2(c1a, lo, hi); u.x = f2h2(lo, hi);
    unpack2(c1b, lo, hi); u.y = f2h2(lo, hi);
    if (row + 1 < N_NODES) th2[(row + 1) * 16 + tx] = u;
    unpack2(c2a, lo, hi); u.x = f2h2(lo, hi);
    unpack2(c2b, lo, hi); u.y = f2h2(lo, hi);
    if (row + 2 < N_NODES) th2[(row + 2) * 16 + tx] = u;
    unpack2(c3a, lo, hi); u.x = f2h2(lo, hi);
    unpack2(c3b, lo, hi); u.y = f2h2(lo, hi);
    if (row + 3 < N_NODES) th2[(row + 3) * 16 + tx] = u;
}

// CSR gather-reduce over fp16 t, no atomics. 16 threads/node, uint2 (4 cols) each.
__global__ void k_agg() {
    unsigned int gid = blockIdx.x * blockDim.x + threadIdx.x;
    unsigned int n = gid >> 4;
    int c = gid & 15;
    if (n >= N_NODES) return;
    const uint2* t2 = (const uint2*)g_th;
    float dn = g_dinv[n];
    uint2 u = t2[n * 16 + c];
    float2 s01 = h2f2(u.x), s23 = h2f2(u.y);
    float w2 = dn * dn;
    float4 acc = make_float4(s01.x * w2, s01.y * w2, s23.x * w2, s23.y * w2);
    int beg = g_off[n];
    int end = beg + g_degi[n];
#pragma unroll 4
    for (int j = beg; j < end; j++) {
        int s = g_esrc[j];             // broadcast across the 16-thread group
        float w = dn * g_dinv[s];
        uint2 uu = t2[s * 16 + c];
        float2 a01 = h2f2(uu.x), a23 = h2f2(uu.y);
        acc.x += a01.x * w; acc.y += a01.y * w;
        acc.z += a23.x * w; acc.w += a23.y * w;
    }
    ((float4*)g_agg)[n * 16 + c] = acc;
}

// h = relu(agg + b1); P = [h@Wm1[0:64]+bm1 | h@Wm1[64:128]] stored fp16.
// Tensor-core version: 8 warps/block, each owns a 16-row x 64-col output tile.
__global__ void k_mm2(const float* __restrict__ Wm1, const float* __restrict__ b1,
                      const float* __restrict__ bm1) {
    __shared__ unsigned short sH[64 * 72];   // h fp16, pitch 72 halves = 36 words
    __shared__ uint2 sB[4 * 16 * 32];        // B frags: [kt][ntile][lane] = 16KB
    __shared__ float sbm[64];
    int tid = threadIdx.x;
    int row0 = blockIdx.x * 64;

    // --- h tile: relu(agg + b1) -> fp16 smem ---
    {
        const float4* agg4 = (const float4*)g_agg;
        const float4* b14 = (const float4*)b1;
        unsigned int* H32 = (unsigned int*)sH;
        for (int i = tid; i < 1024; i += 256) {
            int r = i >> 4, qd = i & 15;
            int row = row0 + r;
            unsigned int w0 = 0, w1 = 0;
            if (row < N_NODES) {
                float4 a = agg4[row * 16 + qd];
                float4 b = b14[qd];
                float vx = fmaxf(a.x + b.x, 0.f), vy = fmaxf(a.y + b.y, 0.f);
                float vz = fmaxf(a.z + b.z, 0.f), vw = fmaxf(a.w + b.w, 0.f);
                w0 = f2h2(vx, vy); w1 = f2h2(vz, vw);
            }
            H32[r * 36 + qd * 2 + 0] = w0;
            H32[r * 36 + qd * 2 + 1] = w1;
        }
    }
    // --- B fragments: effective weight We[k][col] = col<64 ? Wm1[k][col] : Wm1[64+k][col-64] ---
    for (int i = tid; i < 2048; i += 256) {
        int kt = i >> 9, rem = i & 511;
        int nt = rem >> 5, lane2 = rem & 31;
        int gg = lane2 >> 2, qq = lane2 & 3;
        int colg = nt * 8 + gg;
        int rbase = (colg < 64) ? 0 : 64;
        int col = colg & 63;
        int k0 = kt * 16 + 2 * qq;
        uint2 v;
        v.x = f2h2(Wm1[(rbase + k0) * 64 + col],     Wm1[(rbase + k0 + 1) * 64 + col]);
        v.y = f2h2(Wm1[(rbase + k0 + 8) * 64 + col], Wm1[(rbase + k0 + 9) * 64 + col]);
        sB[(kt * 16 + nt) * 32 + lane2] = v;
    }
    if (tid < 64) sbm[tid] = bm1[tid];
    __syncthreads();

    int lane = tid & 31, w = tid >> 5;
    int g = lane >> 2, q = lane & 3;
    int rt = w & 3, ch = w >> 2;      // row tile (16 rows), col half (64 cols)
    int rloc = rt * 16;
    float acc[8][4];
#pragma unroll
    for (int j = 0; j < 8; j++) { acc[j][0] = acc[j][1] = acc[j][2] = acc[j][3] = 0.f; }

    const unsigned int* H32 = (const unsigned int*)sH;
#pragma unroll
    for (int kt = 0; kt < 4; kt++) {
        int base = (rloc + g) * 36 + kt * 8;
        unsigned int a0 = H32[base + q];
        unsigned int a1 = H32[base + 8 * 36 + q];
        unsigned int a2 = H32[base + q + 4];
        unsigned int a3 = H32[base + 8 * 36 + q + 4];
#pragma unroll
        for (int j = 0; j < 8; j++) {
            int nt = ch * 8 + j;
            uint2 b = sB[(kt * 16 + nt) * 32 + lane];
            asm volatile(
                "mma.sync.aligned.m16n8k16.row.col.f32.f16.f16.f32 "
                "{%0,%1,%2,%3}, {%4,%5,%6,%7}, {%8,%9}, {%0,%1,%2,%3};"
                : "+f"(acc[j][0]), "+f"(acc[j][1]), "+f"(acc[j][2]), "+f"(acc[j][3])
                : "r"(a0), "r"(a1), "r"(a2), "r"(a3), "r"(b.x), "r"(b.y));
        }
    }

    // --- epilogue: +bm1 on A-half cols, fp16 pack, store to g_Ph ---
    unsigned int* Ph32 = (unsigned int*)g_Ph;   // 64 half2-words per node row
    int row_g0 = row0 + rloc + g;
    int row_g8 = row_g0 + 8;
#pragma unroll
    for (int j = 0; j < 8; j++) {
        int nt = ch * 8 + j;
        float c0 = acc[j][0], c1 = acc[j][1], c2 = acc[j][2], c3 = acc[j][3];
        if (ch == 0) {                 // cols nt*8+2q < 64: add bm1
            float2 bb = *(const float2*)&sbm[nt * 8 + 2 * q];
            c0 += bb.x; c1 += bb.y; c2 += bb.x; c3 += bb.y;
        }
        int cw = nt * 4 + q;
        if (row_g0 < N_NODES) Ph32[row_g0 * 64 + cw] = f2h2(c0, c1);
        if (row_g8 < N_NODES) Ph32[row_g8 * 64 + cw] = f2h2(c2, c3);
    }
}

// per-edge via tensor cores: G = ea@We on HMMA (m16n8k16), epilogue in-register.
// Each warp owns 16 edges; block = 256 threads = 8 warps = 128 edges; grid = 6250.
__global__ void k_edge(const int* __restrict__ src, const int* __restrict__ dst,
                       const float* __restrict__ ea, const float* __restrict__ Wm1,
                       const float* __restrict__ Wm2, const float* __restrict__ bm2,
                       float* __restrict__ out) {
    __shared__ __align__(16) unsigned short sEA[128 * 16];   // ea tile fp16, pitch 16 halves
    __shared__ unsigned int sB0[8 * 32], sB1[8 * 32];        // B fragments per (tile, lane)
    __shared__ float sW2[64];
    __shared__ float sb2;
    int tid = threadIdx.x;
    int lane = tid & 31, w = tid >> 5;
    int g = lane >> 2, q = lane & 3;
    // --- B fragments for We = Wm1 rows 128..143 (k=16 x n=64), col-tile = tid>>5 ---
    {
        int coln = (tid >> 5) * 8 + g;     // n-column for this (tile, lane)
        int k0 = 2 * q;
        sB0[tid] = f2h2(Wm1[(128 + k0) * 64 + coln],     Wm1[(128 + k0 + 1) * 64 + coln]);
        sB1[tid] = f2h2(Wm1[(128 + k0 + 8) * 64 + coln], Wm1[(128 + k0 + 9) * 64 + coln]);
    }
    if (tid < 64) sW2[tid] = Wm2[tid];
    if (tid == 0) sb2 = bm2[0];
    // --- ea -> smem fp16: thread loads half a row (8 floats) ---
    {
        int eloc = tid >> 1, part = tid & 1;
        size_t e = (size_t)blockIdx.x * 128 + eloc;
        const float4* ea4 = (const float4*)(ea + e * 16) + part * 2;
        float4 v0 = ea4[0], v1 = ea4[1];
        unsigned int* d16 = (unsigned int*)&sEA[eloc * 16 + part * 8];
        d16[0] = f2h2(v0.x, v0.y); d16[1] = f2h2(v0.z, v0.w);
        d16[2] = f2h2(v1.x, v1.y); d16[3] = f2h2(v1.z, v1.w);
    }
    __syncthreads();
    // --- per-warp: 16 edges [wbase, wbase+16) ---
    int wbase = w * 16;
    int r0 = wbase + g, r1 = wbase + g + 8;          // this thread's two edge rows
    unsigned int ebase = blockIdx.x * 128;
    int e0 = ebase + r0, e1 = ebase + r1;
    int s0 = src[e0], d0n = dst[e0];
    int s1 = src[e1], d1n = dst[e1];
    // A fragments (rows r0/r1 of ea tile, halves 2q..2q+1 and 2q+8..2q+9)
    const unsigned int* EA32 = (const unsigned int*)sEA;   // 8 words per edge row
    unsigned int a0 = EA32[r0 * 8 + q];
    unsigned int a1 = EA32[r1 * 8 + q];
    unsigned int a2 = EA32[r0 * 8 + q + 4];
    unsigned int a3 = EA32[r1 * 8 + q + 4];
    const unsigned int* Ph32 = (const unsigned int*)g_Ph;  // 64 half2-words per node
    float acc0 = 0.f, acc1 = 0.f;
#pragma unroll
    for (int j = 0; j < 8; j++) {
        float c0 = 0.f, c1 = 0.f, c2 = 0.f, c3 = 0.f;
        asm volatile(
            "mma.sync.aligned.m16n8k16.row.col.f32.f16.f16.f32 "
            "{%0,%1,%2,%3}, {%4,%5,%6,%7}, {%8,%9}, {%0,%1,%2,%3};"
            : "+f"(c0), "+f"(c1), "+f"(c2), "+f"(c3)
            : "r"(a0), "r"(a1), "r"(a2), "r"(a3),
              "r"(sB0[j * 32 + lane]), "r"(sB1[j * 32 + lane]));
        // cols for this thread: jc = j*8 + 2q, jc+1  -> half2 word j*4+q
        int cw = j * 4 + q;
        unsigned int pa0 = Ph32[s0 * 64 + cw];          // A half (cols 0..63)
        unsigned int pb0 = Ph32[d0n * 64 + 32 + cw];    // B half (cols 64..127)
        unsigned int pa1 = Ph32[s1 * 64 + cw];
        unsigned int pb1 = Ph32[d1n * 64 + 32 + cw];
        float2 h0 = h2f2(hadd2(pa0, pb0));
        float2 h1 = h2f2(hadd2(pa1, pb1));
        c0 = fmaxf(c0 + h0.x, 0.f); c1 = fmaxf(c1 + h0.y, 0.f);
        c2 = fmaxf(c2 + h1.x, 0.f); c3 = fmaxf(c3 + h1.y, 0.f);
        float2 w2v = *(const float2*)&sW2[j * 8 + 2 * q];
        acc0 += c0 * w2v.x + c1 * w2v.y;
        acc1 += c2 * w2v.x + c3 * w2v.y;
    }
    // reduce across the 4 lanes sharing each edge row (lanes g*4 .. g*4+3)
    acc0 += __shfl_xor_sync(0xffffffffu, acc0, 1);
    acc0 += __shfl_xor_sync(0xffffffffu, acc0, 2);
    acc1 += __shfl_xor_sync(0xffffffffu, acc1, 1);
    acc1 += __shfl_xor_sync(0xffffffffu, acc1, 2);
    if (q == 0) {
        out[e0] = 1.f / (1.f + __expf(-(acc0 + sb2)));
        out[e1] = 1.f / (1.f + __expf(-(acc1 + sb2)));
    }
}

extern "C" void kernel_launch(void* const* d_in, const int* in_sizes, int n_in,
                              void* d_out, int out_size) {
    const float* x   = (const float*)d_in[0];
    const int*   src = (const int*)d_in[1];
    const int*   dst = (const int*)d_in[2];
    const float* ea  = (const float*)d_in[3];
    const float* W1  = (const float*)d_in[4];
    const float* b1  = (const float*)d_in[5];
    const float* Wm1 = (const float*)d_in[6];
    const float* bm1 = (const float*)d_in[7];
    const float* Wm2 = (const float*)d_in[8];
    const float* bm2 = (const float*)d_in[9];
    float* out = (float*)d_out;
    (void)in_sizes; (void)n_in; (void)out_size;

    // One-time host-side setup (first call is the uncaptured correctness run;
    // no device memory is allocated here).
    static cudaStream_t s_side = nullptr;
    static cudaEvent_t  s_fork = nullptr, s_join = nullptr;
    static void* degi_ptr = nullptr;
    if (!s_side) {
        cudaStreamCreateWithFlags(&s_side, cudaStreamNonBlocking);
        cudaEventCreateWithFlags(&s_fork, cudaEventDisableTiming);
        cudaEventCreateWithFlags(&s_join, cudaEventDisableTiming);
        cudaGetSymbolAddress(&degi_ptr, g_degi);
    }

    // Fork: k_mm1 (independent of graph structure) overlaps the CSR build chain.
    cudaEventRecord(s_fork, 0);
    cudaStreamWaitEvent(s_side, s_fork, 0);
    k_mm1<<<(N_NODES + 63) / 64, 256, 0, s_side>>>(x, W1);
    cudaEventRecord(s_join, s_side);

    // Main stream: degree histogram -> fused scan -> CSR fill
    cudaMemsetAsync(degi_ptr, 0, N_NODES * sizeof(int), 0);
    k_count<<<(N_EDGES + 255) / 256, 256>>>(dst);
    k_scan<<<NB_SCAN, 1024>>>();
    k_fill<<<(N_EDGES + 255) / 256, 256>>>(src, dst);

    // Join: k_agg needs both k_mm1 (t) and k_fill (CSR)
    cudaStreamWaitEvent(0, s_join, 0);
    k_agg<<<(N_NODES * 16 + 255) / 256, 256>>>();
    k_mm2<<<(N_NODES + 63) / 64, 256>>>(Wm1, b1, bm1);
    k_edge<<<N_EDGES / 128, 256>>>(src, dst, ea, Wm1, Wm2, bm2, out);
}